// round 1
// baseline (speedup 1.0000x reference)
#include <cuda_runtime.h>

#define D_MODEL 1024
#define NHEAD   16
#define HDIM    64
#define BATCH   4
#define SEQ     2048
#define MTOT    (BATCH*SEQ)   // 8192

// Scratch (static device globals: allocation-free, graph-capture safe)
__device__ __align__(16) float g_q  [(size_t)BATCH*NHEAD*SEQ*HDIM];
__device__ __align__(16) float g_k  [(size_t)BATCH*NHEAD*SEQ*HDIM];
__device__ __align__(16) float g_v  [(size_t)BATCH*NHEAD*SEQ*HDIM];
__device__ __align__(16) float g_ctx[(size_t)MTOT*D_MODEL];

// ---------------------------------------------------------------------------
// SGEMM: C[m,n] = sum_k A[m,k] * W[n,k] + bias[n]
// BM=BN=128, BK=8, 256 threads, 8x8 per-thread microtile.
// ---------------------------------------------------------------------------
#define BM 128
#define BN 128
#define BK 8
#define SPAD 132   // padded row length for As/Bs (conflict-free transposed stores)

// Shared GEMM mainloop. Produces acc[8][8]. A: [M,K] rm, W: [N,K] rm.
#define GEMM_BODY(A_PTR, W_PTR)                                             \
  __shared__ float As[BK][SPAD];                                            \
  __shared__ float Bs[BK][SPAD];                                            \
  const int tid  = threadIdx.x;                                             \
  const int rowL = tid >> 1;            /* 0..127 */                        \
  const int colL = (tid & 1) << 2;      /* 0 or 4 */                        \
  const int tr   = tid >> 4;            /* 0..15 */                         \
  const int tc   = tid & 15;            /* 0..15 */                         \
  const float* Ap = (A_PTR) + (size_t)(blockIdx.y * BM) * D_MODEL;          \
  const float* Wp = (W_PTR) + (size_t)(blockIdx.x * BN) * D_MODEL;          \
  float acc[8][8];                                                          \
  _Pragma("unroll")                                                         \
  for (int i = 0; i < 8; i++)                                               \
    _Pragma("unroll")                                                       \
    for (int j = 0; j < 8; j++) acc[i][j] = 0.f;                            \
  for (int k0 = 0; k0 < D_MODEL; k0 += BK) {                                \
    float4 a4 = *(const float4*)(Ap + (size_t)rowL * D_MODEL + k0 + colL);  \
    float4 b4 = *(const float4*)(Wp + (size_t)rowL * D_MODEL + k0 + colL);  \
    As[colL+0][rowL] = a4.x; As[colL+1][rowL] = a4.y;                       \
    As[colL+2][rowL] = a4.z; As[colL+3][rowL] = a4.w;                       \
    Bs[colL+0][rowL] = b4.x; Bs[colL+1][rowL] = b4.y;                       \
    Bs[colL+2][rowL] = b4.z; Bs[colL+3][rowL] = b4.w;                       \
    __syncthreads();                                                        \
    _Pragma("unroll")                                                       \
    for (int kk = 0; kk < BK; kk++) {                                       \
      float4 a0 = *(const float4*)&As[kk][tr*8];                            \
      float4 a1 = *(const float4*)&As[kk][tr*8+4];                          \
      float4 b0 = *(const float4*)&Bs[kk][tc*8];                            \
      float4 b1 = *(const float4*)&Bs[kk][tc*8+4];                          \
      float ra[8] = {a0.x,a0.y,a0.z,a0.w,a1.x,a1.y,a1.z,a1.w};              \
      float rb[8] = {b0.x,b0.y,b0.z,b0.w,b1.x,b1.y,b1.z,b1.w};              \
      _Pragma("unroll")                                                     \
      for (int i = 0; i < 8; i++)                                           \
        _Pragma("unroll")                                                   \
        for (int j = 0; j < 8; j++) acc[i][j] += ra[i] * rb[j];             \
    }                                                                       \
    __syncthreads();                                                        \
  }

// QKV projection: grid (8, 64, 3); z picks {Q,K,V}. Scatters into [B,H,S,Dh].
__global__ __launch_bounds__(256) void proj_qkv_kernel(
    const float* __restrict__ x,
    const float* __restrict__ Wq, const float* __restrict__ bq,
    const float* __restrict__ Wk, const float* __restrict__ bk,
    const float* __restrict__ Wv, const float* __restrict__ bv)
{
  const float* W; const float* bias; float* dst;
  if      (blockIdx.z == 0) { W = Wq; bias = bq; dst = g_q; }
  else if (blockIdx.z == 1) { W = Wk; bias = bk; dst = g_k; }
  else                      { W = Wv; bias = bv; dst = g_v; }

  GEMM_BODY(x, W)

  const int mb = blockIdx.y * BM + tr * 8;
  const int nb = blockIdx.x * BN + tc * 8;
  #pragma unroll
  for (int i = 0; i < 8; i++) {
    const int m = mb + i;
    const int b = m >> 11;         // / SEQ
    const int s = m & (SEQ - 1);
    #pragma unroll
    for (int j = 0; j < 8; j++) {
      const int n = nb + j;
      const int h = n >> 6;        // / HDIM
      const int d = n & (HDIM - 1);
      dst[((((size_t)b * NHEAD + h) * SEQ) + s) * HDIM + d] = acc[i][j] + bias[n];
    }
  }
}

// Output projection: out = ctx @ Wo^T + bo, plain row-major out.
__global__ __launch_bounds__(256) void out_proj_kernel(
    const float* __restrict__ Wo, const float* __restrict__ bo,
    float* __restrict__ out)
{
  GEMM_BODY(g_ctx, Wo)

  const int mb = blockIdx.y * BM + tr * 8;
  const int nb = blockIdx.x * BN + tc * 8;
  #pragma unroll
  for (int i = 0; i < 8; i++) {
    const int m = mb + i;
    #pragma unroll
    for (int j = 0; j < 8; j++) {
      const int n = nb + j;
      out[(size_t)m * D_MODEL + n] = acc[i][j] + bo[n];
    }
  }
}

// ---------------------------------------------------------------------------
// Flash attention, fp32, streaming softmax.
// One block per (b, h, 64-query tile). 256 threads (16x16), 4x4 microtiles.
// Smem: Qs[d][q] pad68, Ks[d][k] pad68, Vs[k][d] pad68, Ps[k][q] pad65.
// ---------------------------------------------------------------------------
#define QPAD 68
#define PPAD 65
#define ATT_SMEM_FLOATS (3*64*QPAD + 64*PPAD)
#define ATT_SMEM_BYTES  (ATT_SMEM_FLOATS * 4)

__global__ __launch_bounds__(256) void attn_kernel()
{
  extern __shared__ float sm[];
  float* Qs = sm;                 // [64][68] index d*68+q
  float* Ks = sm + 64*QPAD;       // [64][68] index d*68+k
  float* Vs = sm + 2*64*QPAD;     // [64][68] index k*68+d
  float* Ps = sm + 3*64*QPAD;     // [64][65] index k*65+q

  const int b  = blockIdx.z;
  const int h  = blockIdx.y;
  const int q0 = blockIdx.x * 64;
  const int tid = threadIdx.x;
  const int tr = tid >> 4;        // 0..15
  const int tc = tid & 15;        // 0..15
  const int qr = tr << 2;         // this thread's 4 query rows
  const int cc = tc << 2;         // this thread's 4 cols (k for S, d for O)

  const float* Qp = g_q + (((size_t)(b * NHEAD + h)) * SEQ + q0) * HDIM;
  const float* Kp = g_k + ((size_t)(b * NHEAD + h)) * SEQ * HDIM;
  const float* Vp = g_v + ((size_t)(b * NHEAD + h)) * SEQ * HDIM;
  const float scale = 0.125f;     // 1/sqrt(64)

  // Load Q tile transposed + pre-scaled
  for (int i = tid; i < 64 * 16; i += 256) {
    const int q = i >> 4;
    const int d = (i & 15) << 2;
    float4 v4 = *(const float4*)(Qp + q * HDIM + d);
    Qs[(d+0)*QPAD + q] = v4.x * scale;
    Qs[(d+1)*QPAD + q] = v4.y * scale;
    Qs[(d+2)*QPAD + q] = v4.z * scale;
    Qs[(d+3)*QPAD + q] = v4.w * scale;
  }

  float mr[4], lr[4], o[4][4];
  #pragma unroll
  for (int i = 0; i < 4; i++) {
    mr[i] = -1e30f; lr[i] = 0.f;
    #pragma unroll
    for (int j = 0; j < 4; j++) o[i][j] = 0.f;
  }

  for (int kt = 0; kt < SEQ; kt += 64) {
    __syncthreads();   // previous iteration's Ps/Vs reads done
    // Load K tile (transposed) and V tile (natural)
    for (int i = tid; i < 64 * 16; i += 256) {
      const int k = i >> 4;
      const int d = (i & 15) << 2;
      float4 k4 = *(const float4*)(Kp + (size_t)(kt + k) * HDIM + d);
      Ks[(d+0)*QPAD + k] = k4.x;
      Ks[(d+1)*QPAD + k] = k4.y;
      Ks[(d+2)*QPAD + k] = k4.z;
      Ks[(d+3)*QPAD + k] = k4.w;
      float4 vv = *(const float4*)(Vp + (size_t)(kt + k) * HDIM + d);
      *(float4*)(Vs + k*QPAD + d) = vv;
    }
    __syncthreads();

    // S = Q K^T (4x4 per thread)
    float s[4][4];
    #pragma unroll
    for (int i = 0; i < 4; i++)
      #pragma unroll
      for (int j = 0; j < 4; j++) s[i][j] = 0.f;

    #pragma unroll 8
    for (int d = 0; d < 64; d++) {
      float4 qa = *(const float4*)(Qs + d*QPAD + qr);
      float4 kb = *(const float4*)(Ks + d*QPAD + cc);
      const float ra[4] = {qa.x, qa.y, qa.z, qa.w};
      const float rb[4] = {kb.x, kb.y, kb.z, kb.w};
      #pragma unroll
      for (int i = 0; i < 4; i++)
        #pragma unroll
        for (int j = 0; j < 4; j++) s[i][j] += ra[i] * rb[j];
    }

    // Online softmax (row reductions across the 16-lane half-warp group)
    #pragma unroll
    for (int i = 0; i < 4; i++) {
      float tmax = fmaxf(fmaxf(s[i][0], s[i][1]), fmaxf(s[i][2], s[i][3]));
      #pragma unroll
      for (int off = 1; off < 16; off <<= 1)
        tmax = fmaxf(tmax, __shfl_xor_sync(0xffffffffu, tmax, off));
      const float mnew = fmaxf(mr[i], tmax);
      const float corr = __expf(mr[i] - mnew);
      mr[i] = mnew;
      float rs = 0.f;
      #pragma unroll
      for (int j = 0; j < 4; j++) {
        s[i][j] = __expf(s[i][j] - mnew);
        rs += s[i][j];
      }
      #pragma unroll
      for (int off = 1; off < 16; off <<= 1)
        rs += __shfl_xor_sync(0xffffffffu, rs, off);
      lr[i] = lr[i] * corr + rs;
      #pragma unroll
      for (int j = 0; j < 4; j++) o[i][j] *= corr;
      // stage P transposed: Ps[k][q]
      #pragma unroll
      for (int j = 0; j < 4; j++)
        Ps[(cc + j)*PPAD + qr + i] = s[i][j];
    }
    __syncthreads();

    // O += P^T V  (reads Ps rows broadcast within half-warp, Vs vectorized)
    #pragma unroll 8
    for (int k = 0; k < 64; k++) {
      const float p0 = Ps[k*PPAD + qr + 0];
      const float p1 = Ps[k*PPAD + qr + 1];
      const float p2 = Ps[k*PPAD + qr + 2];
      const float p3 = Ps[k*PPAD + qr + 3];
      float4 vv = *(const float4*)(Vs + k*QPAD + cc);
      const float rv[4] = {vv.x, vv.y, vv.z, vv.w};
      #pragma unroll
      for (int j = 0; j < 4; j++) {
        o[0][j] += p0 * rv[j];
        o[1][j] += p1 * rv[j];
        o[2][j] += p2 * rv[j];
        o[3][j] += p3 * rv[j];
      }
    }
  }

  // Epilogue: normalize, write ctx in [B, S, D_MODEL] layout
  float* Cp = g_ctx + ((size_t)(b * SEQ + q0)) * D_MODEL + h * HDIM;
  #pragma unroll
  for (int i = 0; i < 4; i++) {
    const float inv = 1.f / lr[i];
    float4 ov;
    ov.x = o[i][0] * inv;
    ov.y = o[i][1] * inv;
    ov.z = o[i][2] * inv;
    ov.w = o[i][3] * inv;
    *(float4*)(Cp + (size_t)(qr + i) * D_MODEL + cc) = ov;
  }
}

// ---------------------------------------------------------------------------
// Launch
// ---------------------------------------------------------------------------
extern "C" void kernel_launch(void* const* d_in, const int* in_sizes, int n_in,
                              void* d_out, int out_size)
{
  const float* x  = (const float*)d_in[0];
  const float* Wq = (const float*)d_in[1];
  const float* bq = (const float*)d_in[2];
  const float* Wk = (const float*)d_in[3];
  const float* bk = (const float*)d_in[4];
  const float* Wv = (const float*)d_in[5];
  const float* bv = (const float*)d_in[6];
  const float* Wo = (const float*)d_in[7];
  const float* bo = (const float*)d_in[8];
  float* out = (float*)d_out;

  cudaFuncSetAttribute(attn_kernel,
                       cudaFuncAttributeMaxDynamicSharedMemorySize,
                       ATT_SMEM_BYTES);

  dim3 gProj(D_MODEL / BN, MTOT / BM, 3);   // (8, 64, 3)
  proj_qkv_kernel<<<gProj, 256>>>(x, Wq, bq, Wk, bk, Wv, bv);

  dim3 gAttn(SEQ / 64, NHEAD, BATCH);       // (32, 16, 4)
  attn_kernel<<<gAttn, 256, ATT_SMEM_BYTES>>>();

  dim3 gOut(D_MODEL / BN, MTOT / BM);       // (8, 64)
  out_proj_kernel<<<gOut, 256>>>(Wo, bo, out);
}